// round 11
// baseline (speedup 1.0000x reference)
#include <cuda_runtime.h>
#include <cuda_bf16.h>
#include <cstdint>

// BTT layer: B=4096, M1=M2=N1=N2=64, R=4.
//   stage1 (per m2): C[4096x256] = x[:, m2*64:+64] @ W1[m2]   (K=64)
//   stage2 (per n1): y[:, n1*64:+64] = t[n1] @ W2[n1]         (K=256)
// bf16 hi/lo split, 3 combos -> ~6e-6 rel err.
// t packed (hi|lo) u32, layout [n1][m2][b][r]; 4 slabs interleaved (L2-resident).
// R11: smaller CTA tiles + launch_bounds(256,3) -> 3 CTAs/SM (occ 33%) to hide
//      L2 latency; A fragments still built directly from global, no mainloop barriers.

#define NB 4096
#define SLAB 1024

__device__ uint4 g_t[16777216];     // 256MB: uint4 idx = (n1*64+m2)*4096 + b
__device__ uint4 g_w1hi[131072];    // [m2][n=256][k-octet=8] (2MB)
__device__ uint4 g_w1lo[131072];
__device__ uint4 g_w2hi[131072];    // [n1][n2=64][k-octet=32] (2MB)
__device__ uint4 g_w2lo[131072];

__device__ __forceinline__ uint32_t fsplit_pack(float v) {
    __nv_bfloat16 h = __float2bfloat16(v);
    float rem = v - __bfloat162float(h);
    __nv_bfloat16 l = __float2bfloat16(rem);
    return (uint32_t)__bfloat16_as_ushort(h) | ((uint32_t)__bfloat16_as_ushort(l) << 16);
}
__device__ __forceinline__ void mma16816(float* c, const uint32_t* a, const uint32_t* b) {
    asm volatile("mma.sync.aligned.m16n8k16.row.col.f32.bf16.bf16.f32 "
        "{%0,%1,%2,%3}, {%4,%5,%6,%7}, {%8,%9}, {%0,%1,%2,%3};"
        : "+f"(c[0]), "+f"(c[1]), "+f"(c[2]), "+f"(c[3])
        : "r"(a[0]), "r"(a[1]), "r"(a[2]), "r"(a[3]), "r"(b[0]), "r"(b[1]));
}
__device__ __forceinline__ void ldsm4(uint32_t* r, uint32_t addr) {
    asm volatile("ldmatrix.sync.aligned.m8n8.x4.shared.b16 {%0,%1,%2,%3}, [%4];"
        : "=r"(r[0]), "=r"(r[1]), "=r"(r[2]), "=r"(r[3]) : "r"(addr));
}

// SMEM row stride 144B (72 bf16): conflict-free for LDSM 8-row x 16B phases.
#define RS 144

// ---------------- prep: split weights into [outer][k] bf16 hi/lo ------------
__global__ void prep_w1_kernel(const float* __restrict__ W1) {
    const int m2 = blockIdx.x, n = threadIdx.x;
    const float* Wm = W1 + (size_t)m2 * 16384;
    #pragma unroll
    for (int j = 0; j < 8; j++) {
        uint32_t p[8];
        #pragma unroll
        for (int kk = 0; kk < 8; kk++) p[kk] = fsplit_pack(Wm[(8 * j + kk) * 256 + n]);
        const int idx = (m2 * 256 + n) * 8 + j;
        g_w1hi[idx] = make_uint4(__byte_perm(p[0], p[1], 0x5410), __byte_perm(p[2], p[3], 0x5410),
                                 __byte_perm(p[4], p[5], 0x5410), __byte_perm(p[6], p[7], 0x5410));
        g_w1lo[idx] = make_uint4(__byte_perm(p[0], p[1], 0x7632), __byte_perm(p[2], p[3], 0x7632),
                                 __byte_perm(p[4], p[5], 0x7632), __byte_perm(p[6], p[7], 0x7632));
    }
}
__global__ void prep_w2_kernel(const float* __restrict__ W2) {
    const int n1 = blockIdx.x, tid = threadIdx.x;
    const int n2 = tid & 63, kq = tid >> 6;
    const float* Wn = W2 + (size_t)n1 * 16384;
    #pragma unroll
    for (int j = 0; j < 8; j++) {
        const int k0 = kq * 64 + j * 8;
        uint32_t p[8];
        #pragma unroll
        for (int kk = 0; kk < 8; kk++) p[kk] = fsplit_pack(Wn[(k0 + kk) * 64 + n2]);
        const int idx = (n1 * 64 + n2) * 32 + kq * 8 + j;
        g_w2hi[idx] = make_uint4(__byte_perm(p[0], p[1], 0x5410), __byte_perm(p[2], p[3], 0x5410),
                                 __byte_perm(p[4], p[5], 0x5410), __byte_perm(p[6], p[7], 0x5410));
        g_w2lo[idx] = make_uint4(__byte_perm(p[0], p[1], 0x7632), __byte_perm(p[2], p[3], 0x7632),
                                 __byte_perm(p[4], p[5], 0x7632), __byte_perm(p[6], p[7], 0x7632));
    }
}

// ---------------- stage 1: tile 128(b) x 64(n), K=64 ------------------------
// SMEM: B tiles only (64 n rows, hi+lo). A fragments direct from x.
#define S1_BHI 0
#define S1_BLO 9216
#define S1_SMEM 18432

__global__ void __launch_bounds__(256, 3)
stage1_kernel(const float* __restrict__ x, int bslab) {
    extern __shared__ char smem[];
    const uint32_t sb = (uint32_t)__cvta_generic_to_shared(smem);
    const int tid = threadIdx.x, wid = tid >> 5, lane = tid & 31;
    const int m2 = blockIdx.x, b0 = bslab + blockIdx.y * 128, nbase = blockIdx.z * 64;

    {   // B fill: 64 rows x 8 uint4 per plane
        const uint4* bh = g_w1hi + (m2 * 256 + nbase) * 8;
        const uint4* bl = g_w1lo + (m2 * 256 + nbase) * 8;
        #pragma unroll
        for (int i = 0; i < 2; i++) {
            const int idx = tid + 256 * i;        // 512 uint4
            const int row = idx >> 3, q = idx & 7;
            *(uint4*)(smem + S1_BHI + row * RS + q * 16) = bh[idx];
            *(uint4*)(smem + S1_BLO + row * RS + q * 16) = bl[idx];
        }
    }
    __syncthreads();   // the only barrier

    const int wr = wid >> 1, wc = wid & 1, qr = lane >> 2, qc = lane & 3;
    const uint32_t laneB = (uint32_t)((wc * 32 + (lane & 7) + ((lane & 16) ? 8 : 0)) * RS +
                                      ((lane & 8) ? 16 : 0));
    const int row0 = b0 + wr * 32 + qr;

    float acc[2][4][4];
    #pragma unroll
    for (int mt = 0; mt < 2; mt++)
        #pragma unroll
        for (int nt = 0; nt < 4; nt++)
            #pragma unroll
            for (int r = 0; r < 4; r++) acc[mt][nt][r] = 0.f;

    #pragma unroll
    for (int ks = 0; ks < 4; ks++) {
        const int k0 = ks * 16 + 2 * qc;
        uint32_t ah[2][4], al[2][4];
        #pragma unroll
        for (int mt = 0; mt < 2; mt++) {
            const float* xr = x + (size_t)(row0 + mt * 16) * 4096 + m2 * 64;
            float2 f0 = *(const float2*)(xr + k0);
            float2 f1 = *(const float2*)(xr + (size_t)8 * 4096 + k0);
            float2 f2 = *(const float2*)(xr + k0 + 8);
            float2 f3 = *(const float2*)(xr + (size_t)8 * 4096 + k0 + 8);
            uint32_t q0 = fsplit_pack(f0.x), q1 = fsplit_pack(f0.y);
            uint32_t q2 = fsplit_pack(f1.x), q3 = fsplit_pack(f1.y);
            uint32_t q4 = fsplit_pack(f2.x), q5 = fsplit_pack(f2.y);
            uint32_t q6 = fsplit_pack(f3.x), q7 = fsplit_pack(f3.y);
            ah[mt][0] = __byte_perm(q0, q1, 0x5410); al[mt][0] = __byte_perm(q0, q1, 0x7632);
            ah[mt][1] = __byte_perm(q2, q3, 0x5410); al[mt][1] = __byte_perm(q2, q3, 0x7632);
            ah[mt][2] = __byte_perm(q4, q5, 0x5410); al[mt][2] = __byte_perm(q4, q5, 0x7632);
            ah[mt][3] = __byte_perm(q6, q7, 0x5410); al[mt][3] = __byte_perm(q6, q7, 0x7632);
        }
        uint32_t b[4][2];
        {   // Bh: (Ah + Al) x Bh
            uint32_t r[4];
            ldsm4(r, sb + S1_BHI + laneB + ks * 32);
            b[0][0] = r[0]; b[0][1] = r[1]; b[1][0] = r[2]; b[1][1] = r[3];
            ldsm4(r, sb + S1_BHI + laneB + 16 * RS + ks * 32);
            b[2][0] = r[0]; b[2][1] = r[1]; b[3][0] = r[2]; b[3][1] = r[3];
        }
        #pragma unroll
        for (int mt = 0; mt < 2; mt++)
            #pragma unroll
            for (int nt = 0; nt < 4; nt++) {
                mma16816(acc[mt][nt], ah[mt], b[nt]);
                mma16816(acc[mt][nt], al[mt], b[nt]);
            }
        {   // Bl: Ah x Bl (reuse b regs)
            uint32_t r[4];
            ldsm4(r, sb + S1_BLO + laneB + ks * 32);
            b[0][0] = r[0]; b[0][1] = r[1]; b[1][0] = r[2]; b[1][1] = r[3];
            ldsm4(r, sb + S1_BLO + laneB + 16 * RS + ks * 32);
            b[2][0] = r[0]; b[2][1] = r[1]; b[3][0] = r[2]; b[3][1] = r[3];
        }
        #pragma unroll
        for (int mt = 0; mt < 2; mt++)
            #pragma unroll
            for (int nt = 0; nt < 4; nt++)
                mma16816(acc[mt][nt], ah[mt], b[nt]);
    }

    // epilogue -> g_t[n1][m2][b][r]
    uint2* gt2 = (uint2*)g_t;
    #pragma unroll
    for (int mt = 0; mt < 2; mt++) {
        const size_t rw = (size_t)(row0 + mt * 16);
        #pragma unroll
        for (int nt = 0; nt < 4; nt++) {
            const int cg = nbase + wc * 32 + nt * 8 + qc * 2;   // n = n1*4 + r
            const size_t base = (((size_t)(cg >> 2) * 64 + m2) * 4096) * 4 + (cg & 3);
            gt2[(base + rw * 4) >> 1] =
                make_uint2(fsplit_pack(acc[mt][nt][0]), fsplit_pack(acc[mt][nt][1]));
            gt2[(base + (rw + 8) * 4) >> 1] =
                make_uint2(fsplit_pack(acc[mt][nt][2]), fsplit_pack(acc[mt][nt][3]));
        }
    }
}

// ---------------- stage 2: tile 64(b) x 64(n2), K=256 -----------------------
// SMEM: B tiles only; A fragments direct from g_t (L2-resident slab).
#define S2_BHI 0                    // [chunk][64][RS] per half (9216 B/chunk)
#define S2_BLO 36864
#define S2_SMEM 73728

__global__ void __launch_bounds__(256, 3)
stage2_kernel(float* __restrict__ y, int bslab) {
    extern __shared__ char smem[];
    const uint32_t sb = (uint32_t)__cvta_generic_to_shared(smem);
    const int tid = threadIdx.x, wid = tid >> 5, lane = tid & 31;
    const int n1 = blockIdx.x, b0 = bslab + blockIdx.y * 64;

    {   // B fill (once): chunked [chunk][n2][RS]
        const uint4* bh = g_w2hi + n1 * 2048;
        const uint4* bl = g_w2lo + n1 * 2048;
        #pragma unroll
        for (int i = 0; i < 8; i++) {
            const int idx = tid + 256 * i;
            const int n2 = idx >> 5, w = idx & 31;
            const int chunk = w >> 3, q = w & 7;
            const int dst = chunk * 9216 + n2 * RS + q * 16;
            *(uint4*)(smem + S2_BHI + dst) = bh[idx];
            *(uint4*)(smem + S2_BLO + dst) = bl[idx];
        }
    }
    __syncthreads();   // the only barrier

    const int wr = wid >> 1, wc = wid & 1, qr = lane >> 2, qc = lane & 3;
    const uint32_t laneB = (uint32_t)((wc * 32 + (lane & 7) + ((lane & 16) ? 8 : 0)) * RS +
                                      ((lane & 8) ? 16 : 0));
    const int qch = qc >> 1, rr = (qc & 1) * 2;
    const int row0 = b0 + wr * 16 + qr;

    float acc[4][4];
    #pragma unroll
    for (int nt = 0; nt < 4; nt++)
        #pragma unroll
        for (int r = 0; r < 4; r++) acc[nt][r] = 0.f;

    const uint32_t* tb = (const uint32_t*)g_t + (size_t)n1 * 64 * 16384;

    #pragma unroll
    for (int g = 0; g < 16; g++) {                    // g = global k16 index
        const uint32_t* pA = tb + (size_t)(4 * g + qch) * 16384;
        const uint32_t* pB = pA + 2 * 16384;
        uint2 x0 = *(const uint2*)(pA + (size_t)row0 * 4 + rr);
        uint2 x1 = *(const uint2*)(pA + (size_t)(row0 + 8) * 4 + rr);
        uint2 x2 = *(const uint2*)(pB + (size_t)row0 * 4 + rr);
        uint2 x3 = *(const uint2*)(pB + (size_t)(row0 + 8) * 4 + rr);
        uint32_t ah[4], al[4];
        ah[0] = __byte_perm(x0.x, x0.y, 0x5410); al[0] = __byte_perm(x0.x, x0.y, 0x7632);
        ah[1] = __byte_perm(x1.x, x1.y, 0x5410); al[1] = __byte_perm(x1.x, x1.y, 0x7632);
        ah[2] = __byte_perm(x2.x, x2.y, 0x5410); al[2] = __byte_perm(x2.x, x2.y, 0x7632);
        ah[3] = __byte_perm(x3.x, x3.y, 0x5410); al[3] = __byte_perm(x3.x, x3.y, 0x7632);

        const int ch = g >> 2, ksl = g & 3;
        uint32_t b[4][2];
        {   // Bh: Ah·Bh + Al·Bh
            uint32_t r[4];
            ldsm4(r, sb + S2_BHI + ch * 9216 + laneB + ksl * 32);
            b[0][0] = r[0]; b[0][1] = r[1]; b[1][0] = r[2]; b[1][1] = r[3];
            ldsm4(r, sb + S2_BHI + ch * 9216 + laneB + 16 * RS + ksl * 32);
            b[2][0] = r[0]; b[2][1] = r[1]; b[3][0] = r[2]; b[3][1] = r[3];
        }
        #pragma unroll
        for (int nt = 0; nt < 4; nt++) {
            mma16816(acc[nt], ah, b[nt]);
            mma16816(acc[nt], al, b[nt]);
        }
        {   // Bl: Ah·Bl (reuse b regs)
            uint32_t r[4];
            ldsm4(r, sb + S2_BLO + ch * 9216 + laneB + ksl * 32);
            b[0][0] = r[0]; b[0][1] = r[1]; b[1][0] = r[2]; b[1][1] = r[3];
            ldsm4(r, sb + S2_BLO + ch * 9216 + laneB + 16 * RS + ksl * 32);
            b[2][0] = r[0]; b[2][1] = r[1]; b[3][0] = r[2]; b[3][1] = r[3];
        }
        #pragma unroll
        for (int nt = 0; nt < 4; nt++)
            mma16816(acc[nt], ah, b[nt]);
    }

    // epilogue: y[b][n1*64 + n2]
    #pragma unroll
    for (int nt = 0; nt < 4; nt++) {
        const int col = n1 * 64 + wc * 32 + nt * 8 + qc * 2;
        *(float2*)(y + (size_t)row0 * 4096 + col) = make_float2(acc[nt][0], acc[nt][1]);
        *(float2*)(y + (size_t)(row0 + 8) * 4096 + col) = make_float2(acc[nt][2], acc[nt][3]);
    }
}

// ---------------------------------------------------------------------------
extern "C" void kernel_launch(void* const* d_in, const int* in_sizes, int n_in,
                              void* d_out, int out_size) {
    const float* x  = (const float*)d_in[0];
    const float* W1 = (const float*)d_in[1];
    const float* W2 = (const float*)d_in[2];
    float* y = (float*)d_out;

    cudaFuncSetAttribute(stage1_kernel, cudaFuncAttributeMaxDynamicSharedMemorySize, S1_SMEM);
    cudaFuncSetAttribute(stage2_kernel, cudaFuncAttributeMaxDynamicSharedMemorySize, S2_SMEM);

    prep_w1_kernel<<<64, 256>>>(W1);
    prep_w2_kernel<<<64, 256>>>(W2);
    // Interleave slabs so each slab's t (64MB) is consumed while L2-resident.
    for (int s = 0; s < 4; s++) {
        stage1_kernel<<<dim3(64, SLAB / 128, 4), 256, S1_SMEM>>>(x, s * SLAB);
        stage2_kernel<<<dim3(64, SLAB / 64), 256, S2_SMEM>>>(y, s * SLAB);
    }
}

// round 12
// speedup vs baseline: 1.1457x; 1.1457x over previous
#include <cuda_runtime.h>
#include <cuda_bf16.h>
#include <cstdint>

// BTT layer: B=4096, M1=M2=N1=N2=64, R=4.
//   stage1 (per m2): C[4096x256] = x[:, m2*64:+64] @ W1[m2]   (K=64)
//   stage2 (per n1): y[:, n1*64:+64] = t[n1] @ W2[n1]         (K=256)
// bf16 hi/lo split, 3 combos -> ~6e-6 rel err.
// t packed (hi|lo) u32, layout [n1][m2][b][r]; 4 slabs interleaved (L2-resident).
// R12: stage1 = R10 (best known). stage2: 8 row-band warps (t read once),
//      next-g register prefetch -> LDG latency hidden under MMAs.

#define NB 4096
#define SLAB 1024

__device__ uint4 g_t[16777216];     // 256MB: uint4 idx = (n1*64+m2)*4096 + b
__device__ uint4 g_w1hi[131072];    // [m2][n=256][k-octet=8] (2MB)
__device__ uint4 g_w1lo[131072];
__device__ uint4 g_w2hi[131072];    // [n1][n2=64][k-octet=32] (2MB)
__device__ uint4 g_w2lo[131072];

__device__ __forceinline__ uint32_t fsplit_pack(float v) {
    __nv_bfloat16 h = __float2bfloat16(v);
    float rem = v - __bfloat162float(h);
    __nv_bfloat16 l = __float2bfloat16(rem);
    return (uint32_t)__bfloat16_as_ushort(h) | ((uint32_t)__bfloat16_as_ushort(l) << 16);
}
__device__ __forceinline__ void mma16816(float* c, const uint32_t* a, const uint32_t* b) {
    asm volatile("mma.sync.aligned.m16n8k16.row.col.f32.bf16.bf16.f32 "
        "{%0,%1,%2,%3}, {%4,%5,%6,%7}, {%8,%9}, {%0,%1,%2,%3};"
        : "+f"(c[0]), "+f"(c[1]), "+f"(c[2]), "+f"(c[3])
        : "r"(a[0]), "r"(a[1]), "r"(a[2]), "r"(a[3]), "r"(b[0]), "r"(b[1]));
}
__device__ __forceinline__ void ldsm4(uint32_t* r, uint32_t addr) {
    asm volatile("ldmatrix.sync.aligned.m8n8.x4.shared.b16 {%0,%1,%2,%3}, [%4];"
        : "=r"(r[0]), "=r"(r[1]), "=r"(r[2]), "=r"(r[3]) : "r"(addr));
}

// SMEM row stride 144B (72 bf16): conflict-free for LDSM 8-row x 16B phases.
#define RS 144

// ---------------- prep: split weights into [outer][k] bf16 hi/lo ------------
__global__ void prep_w1_kernel(const float* __restrict__ W1) {
    const int m2 = blockIdx.x, n = threadIdx.x;
    const float* Wm = W1 + (size_t)m2 * 16384;
    #pragma unroll
    for (int j = 0; j < 8; j++) {
        uint32_t p[8];
        #pragma unroll
        for (int kk = 0; kk < 8; kk++) p[kk] = fsplit_pack(Wm[(8 * j + kk) * 256 + n]);
        const int idx = (m2 * 256 + n) * 8 + j;
        g_w1hi[idx] = make_uint4(__byte_perm(p[0], p[1], 0x5410), __byte_perm(p[2], p[3], 0x5410),
                                 __byte_perm(p[4], p[5], 0x5410), __byte_perm(p[6], p[7], 0x5410));
        g_w1lo[idx] = make_uint4(__byte_perm(p[0], p[1], 0x7632), __byte_perm(p[2], p[3], 0x7632),
                                 __byte_perm(p[4], p[5], 0x7632), __byte_perm(p[6], p[7], 0x7632));
    }
}
__global__ void prep_w2_kernel(const float* __restrict__ W2) {
    const int n1 = blockIdx.x, tid = threadIdx.x;
    const int n2 = tid & 63, kq = tid >> 6;
    const float* Wn = W2 + (size_t)n1 * 16384;
    #pragma unroll
    for (int j = 0; j < 8; j++) {
        const int k0 = kq * 64 + j * 8;
        uint32_t p[8];
        #pragma unroll
        for (int kk = 0; kk < 8; kk++) p[kk] = fsplit_pack(Wn[(k0 + kk) * 64 + n2]);
        const int idx = (n1 * 64 + n2) * 32 + kq * 8 + j;
        g_w2hi[idx] = make_uint4(__byte_perm(p[0], p[1], 0x5410), __byte_perm(p[2], p[3], 0x5410),
                                 __byte_perm(p[4], p[5], 0x5410), __byte_perm(p[6], p[7], 0x5410));
        g_w2lo[idx] = make_uint4(__byte_perm(p[0], p[1], 0x7632), __byte_perm(p[2], p[3], 0x7632),
                                 __byte_perm(p[4], p[5], 0x7632), __byte_perm(p[6], p[7], 0x7632));
    }
}

// ---------------- stage 1 (R10, unchanged): tile 128(b) x 128(n), K=64 ------
#define S1_BHI 0
#define S1_BLO 18432
#define S1_SMEM 36864

__global__ void __launch_bounds__(256, 2)
stage1_kernel(const float* __restrict__ x, int bslab) {
    extern __shared__ char smem[];
    const uint32_t sb = (uint32_t)__cvta_generic_to_shared(smem);
    const int tid = threadIdx.x, wid = tid >> 5, lane = tid & 31;
    const int m2 = blockIdx.x, b0 = bslab + blockIdx.y * 128, nbase = blockIdx.z * 128;

    {   // B fill: pre-split images (L2-resident)
        const uint4* bh = g_w1hi + (m2 * 256 + nbase) * 8;
        const uint4* bl = g_w1lo + (m2 * 256 + nbase) * 8;
        #pragma unroll
        for (int i = 0; i < 4; i++) {
            const int idx = tid + 256 * i;
            const int row = idx >> 3, q = idx & 7;
            *(uint4*)(smem + S1_BHI + row * RS + q * 16) = bh[idx];
            *(uint4*)(smem + S1_BLO + row * RS + q * 16) = bl[idx];
        }
    }
    __syncthreads();   // the only barrier

    const int wr = wid >> 1, wc = wid & 1, qr = lane >> 2, qc = lane & 3;
    const uint32_t laneB = (uint32_t)((wc * 64 + (lane & 7) + ((lane & 16) ? 8 : 0)) * RS +
                                      ((lane & 8) ? 16 : 0));
    const int row0 = b0 + wr * 32 + qr;

    float acc[2][8][4];
    #pragma unroll
    for (int mt = 0; mt < 2; mt++)
        #pragma unroll
        for (int nt = 0; nt < 8; nt++)
            #pragma unroll
            for (int r = 0; r < 4; r++) acc[mt][nt][r] = 0.f;

    #pragma unroll
    for (int ks = 0; ks < 4; ks++) {
        const int k0 = ks * 16 + 2 * qc;
        uint32_t ah[2][4], al[2][4];
        #pragma unroll
        for (int mt = 0; mt < 2; mt++) {
            const float* xr = x + (size_t)(row0 + mt * 16) * 4096 + m2 * 64;
            float2 f0 = *(const float2*)(xr + k0);
            float2 f1 = *(const float2*)(xr + (size_t)8 * 4096 + k0);
            float2 f2 = *(const float2*)(xr + k0 + 8);
            float2 f3 = *(const float2*)(xr + (size_t)8 * 4096 + k0 + 8);
            uint32_t q0 = fsplit_pack(f0.x), q1 = fsplit_pack(f0.y);
            uint32_t q2 = fsplit_pack(f1.x), q3 = fsplit_pack(f1.y);
            uint32_t q4 = fsplit_pack(f2.x), q5 = fsplit_pack(f2.y);
            uint32_t q6 = fsplit_pack(f3.x), q7 = fsplit_pack(f3.y);
            ah[mt][0] = __byte_perm(q0, q1, 0x5410); al[mt][0] = __byte_perm(q0, q1, 0x7632);
            ah[mt][1] = __byte_perm(q2, q3, 0x5410); al[mt][1] = __byte_perm(q2, q3, 0x7632);
            ah[mt][2] = __byte_perm(q4, q5, 0x5410); al[mt][2] = __byte_perm(q4, q5, 0x7632);
            ah[mt][3] = __byte_perm(q6, q7, 0x5410); al[mt][3] = __byte_perm(q6, q7, 0x7632);
        }
        {   // group 1: (Ah + Al) x Bh
            uint32_t b[8][2];
            #pragma unroll
            for (int p = 0; p < 4; p++) {
                uint32_t r[4];
                ldsm4(r, sb + S1_BHI + laneB + p * 16 * RS + ks * 32);
                b[2 * p][0] = r[0]; b[2 * p][1] = r[1];
                b[2 * p + 1][0] = r[2]; b[2 * p + 1][1] = r[3];
            }
            #pragma unroll
            for (int mt = 0; mt < 2; mt++)
                #pragma unroll
                for (int nt = 0; nt < 8; nt++) {
                    mma16816(acc[mt][nt], ah[mt], b[nt]);
                    mma16816(acc[mt][nt], al[mt], b[nt]);
                }
        }
        {   // group 2: Ah x Bl
            uint32_t b[8][2];
            #pragma unroll
            for (int p = 0; p < 4; p++) {
                uint32_t r[4];
                ldsm4(r, sb + S1_BLO + laneB + p * 16 * RS + ks * 32);
                b[2 * p][0] = r[0]; b[2 * p][1] = r[1];
                b[2 * p + 1][0] = r[2]; b[2 * p + 1][1] = r[3];
            }
            #pragma unroll
            for (int mt = 0; mt < 2; mt++)
                #pragma unroll
                for (int nt = 0; nt < 8; nt++)
                    mma16816(acc[mt][nt], ah[mt], b[nt]);
        }
    }

    // epilogue -> g_t[n1][m2][b][r]
    uint2* gt2 = (uint2*)g_t;
    #pragma unroll
    for (int mt = 0; mt < 2; mt++) {
        const size_t rw = (size_t)(row0 + mt * 16);
        #pragma unroll
        for (int nt = 0; nt < 8; nt++) {
            const int cg = nbase + wc * 64 + nt * 8 + qc * 2;   // n = n1*4 + r
            const size_t base = (((size_t)(cg >> 2) * 64 + m2) * 4096) * 4 + (cg & 3);
            gt2[(base + rw * 4) >> 1] =
                make_uint2(fsplit_pack(acc[mt][nt][0]), fsplit_pack(acc[mt][nt][1]));
            gt2[(base + (rw + 8) * 4) >> 1] =
                make_uint2(fsplit_pack(acc[mt][nt][2]), fsplit_pack(acc[mt][nt][3]));
        }
    }
}

// ---------------- stage 2: tile 128(b) x 64(n2), K=256 ----------------------
// 8 warps = 8 row-bands of 16 (t read once per CTA); NT=8 full width.
// Register prefetch of next-g A data; B via ldsm from smem.
#define S2_BHI 0                    // [chunk][64][RS] per half (9216 B/chunk)
#define S2_BLO 36864
#define S2_SMEM 73728

__global__ void __launch_bounds__(256, 2)
stage2_kernel(float* __restrict__ y, int bslab) {
    extern __shared__ char smem[];
    const uint32_t sb = (uint32_t)__cvta_generic_to_shared(smem);
    const int tid = threadIdx.x, wid = tid >> 5, lane = tid & 31;
    const int n1 = blockIdx.x, b0 = bslab + blockIdx.y * 128;

    {   // B fill (once): chunked [chunk][n2][RS]
        const uint4* bh = g_w2hi + n1 * 2048;
        const uint4* bl = g_w2lo + n1 * 2048;
        #pragma unroll
        for (int i = 0; i < 8; i++) {
            const int idx = tid + 256 * i;
            const int n2 = idx >> 5, w = idx & 31;
            const int chunk = w >> 3, q = w & 7;
            const int dst = chunk * 9216 + n2 * RS + q * 16;
            *(uint4*)(smem + S2_BHI + dst) = bh[idx];
            *(uint4*)(smem + S2_BLO + dst) = bl[idx];
        }
    }
    __syncthreads();   // the only barrier

    const int qr = lane >> 2, qc = lane & 3;
    const uint32_t laneB = (uint32_t)(((lane & 7) + ((lane & 16) ? 8 : 0)) * RS +
                                      ((lane & 8) ? 16 : 0));
    const int qch = qc >> 1, rr = (qc & 1) * 2;
    const int row0 = b0 + wid * 16 + qr;            // 8 warps x 16 rows

    float acc[8][4];
    #pragma unroll
    for (int nt = 0; nt < 8; nt++)
        #pragma unroll
        for (int r = 0; r < 4; r++) acc[nt][r] = 0.f;

    const uint32_t* tb = (const uint32_t*)g_t + (size_t)n1 * 64 * 16384;

    // prime: load g=0 raw A (4 x uint2)
    uint2 cur[4];
    {
        const uint32_t* pA = tb + (size_t)qch * 16384;
        const uint32_t* pB = pA + 2 * 16384;
        cur[0] = *(const uint2*)(pA + (size_t)row0 * 4 + rr);
        cur[1] = *(const uint2*)(pA + (size_t)(row0 + 8) * 4 + rr);
        cur[2] = *(const uint2*)(pB + (size_t)row0 * 4 + rr);
        cur[3] = *(const uint2*)(pB + (size_t)(row0 + 8) * 4 + rr);
    }

    #pragma unroll
    for (int g = 0; g < 16; g++) {                  // g = global k16 index
        // prefetch g+1 before any dependent compute on cur
        uint2 nxt[4];
        if (g < 15) {
            const uint32_t* pA = tb + (size_t)(4 * (g + 1) + qch) * 16384;
            const uint32_t* pB = pA + 2 * 16384;
            nxt[0] = *(const uint2*)(pA + (size_t)row0 * 4 + rr);
            nxt[1] = *(const uint2*)(pA + (size_t)(row0 + 8) * 4 + rr);
            nxt[2] = *(const uint2*)(pB + (size_t)row0 * 4 + rr);
            nxt[3] = *(const uint2*)(pB + (size_t)(row0 + 8) * 4 + rr);
        }

        uint32_t ah[4], al[4];
        ah[0] = __byte_perm(cur[0].x, cur[0].y, 0x5410); al[0] = __byte_perm(cur[0].x, cur[0].y, 0x7632);
        ah[1] = __byte_perm(cur[1].x, cur[1].y, 0x5410); al[1] = __byte_perm(cur[1].x, cur[1].y, 0x7632);
        ah[2] = __byte_perm(cur[2].x, cur[2].y, 0x5410); al[2] = __byte_perm(cur[2].x, cur[2].y, 0x7632);
        ah[3] = __byte_perm(cur[3].x, cur[3].y, 0x5410); al[3] = __byte_perm(cur[3].x, cur[3].y, 0x7632);

        const int ch = g >> 2, ksl = g & 3;
        uint32_t b[8][2];
        {   // Bh plane: Ah·Bh + Al·Bh (16 MMAs)
            #pragma unroll
            for (int p = 0; p < 4; p++) {
                uint32_t r[4];
                ldsm4(r, sb + S2_BHI + ch * 9216 + laneB + p * 16 * RS + ksl * 32);
                b[2 * p][0] = r[0]; b[2 * p][1] = r[1];
                b[2 * p + 1][0] = r[2]; b[2 * p + 1][1] = r[3];
            }
            #pragma unroll
            for (int nt = 0; nt < 8; nt++) {
                mma16816(acc[nt], ah, b[nt]);
                mma16816(acc[nt], al, b[nt]);
            }
        }
        {   // Bl plane: Ah·Bl (8 MMAs), reuse b regs
            #pragma unroll
            for (int p = 0; p < 4; p++) {
                uint32_t r[4];
                ldsm4(r, sb + S2_BLO + ch * 9216 + laneB + p * 16 * RS + ksl * 32);
                b[2 * p][0] = r[0]; b[2 * p][1] = r[1];
                b[2 * p + 1][0] = r[2]; b[2 * p + 1][1] = r[3];
            }
            #pragma unroll
            for (int nt = 0; nt < 8; nt++)
                mma16816(acc[nt], ah, b[nt]);
        }

        if (g < 15) { cur[0] = nxt[0]; cur[1] = nxt[1]; cur[2] = nxt[2]; cur[3] = nxt[3]; }
    }

    // epilogue: y[b][n1*64 + n2]
    #pragma unroll
    for (int nt = 0; nt < 8; nt++) {
        const int col = n1 * 64 + nt * 8 + qc * 2;
        *(float2*)(y + (size_t)row0 * 4096 + col) = make_float2(acc[nt][0], acc[nt][1]);
        *(float2*)(y + (size_t)(row0 + 8) * 4096 + col) = make_float2(acc[nt][2], acc[nt][3]);
    }
}

// ---------------------------------------------------------------------------
extern "C" void kernel_launch(void* const* d_in, const int* in_sizes, int n_in,
                              void* d_out, int out_size) {
    const float* x  = (const float*)d_in[0];
    const float* W1 = (const float*)d_in[1];
    const float* W2 = (const float*)d_in[2];
    float* y = (float*)d_out;

    cudaFuncSetAttribute(stage1_kernel, cudaFuncAttributeMaxDynamicSharedMemorySize, S1_SMEM);
    cudaFuncSetAttribute(stage2_kernel, cudaFuncAttributeMaxDynamicSharedMemorySize, S2_SMEM);

    prep_w1_kernel<<<64, 256>>>(W1);
    prep_w2_kernel<<<64, 256>>>(W2);
    // Interleave slabs so each slab's t (64MB) is consumed while L2-resident.
    for (int s = 0; s < 4; s++) {
        stage1_kernel<<<dim3(64, SLAB / 128, 2), 256, S1_SMEM>>>(x, s * SLAB);
        stage2_kernel<<<dim3(64, SLAB / 128), 256, S2_SMEM>>>(y, s * SLAB);
    }
}

// round 13
// speedup vs baseline: 1.2203x; 1.0651x over previous
#include <cuda_runtime.h>
#include <cuda_bf16.h>
#include <cstdint>

// BTT layer: B=4096, M1=M2=N1=N2=64, R=4.
//   stage1 (per m2): C[4096x256] = x[:, m2*64:+64] @ W1[m2]   (K=64)
//   stage2 (per n1): y[:, n1*64:+64] = t[n1] @ W2[n1]         (K=256)
// bf16 hi/lo split, 3 combos -> ~6e-6 rel err.
// R13: fsplit2 (cvt.rn.bf16x2.f32 pair-split) everywhere; g_t stores MMA-ready
//      (hi2, lo2) fragment words; stage1 = 8 row-bands x 128n (x read once).
// t layout: u32 idx = ((n1*64+m2)*4096 + b)*4 + slot, slot = {hi2(r01), lo2(r01),
//      hi2(r23), lo2(r23)}. 4 slabs interleaved (L2-resident).

#define NB 4096
#define SLAB 1024

__device__ uint4 g_t[16777216];     // 256MB
__device__ uint4 g_w1hi[131072];    // [m2][n=256][k-octet=8] (2MB)
__device__ uint4 g_w1lo[131072];
__device__ uint4 g_w2hi[131072];    // [n1][n2=64][k-octet=32] (2MB)
__device__ uint4 g_w2lo[131072];

// pair split: w_hi = {bf16(e1)<<16 | bf16(e0)}, w_lo = residual pair. Fragment-ready.
__device__ __forceinline__ void fsplit2(float e0, float e1, uint32_t& w_hi, uint32_t& w_lo) {
    asm("cvt.rn.bf16x2.f32 %0, %1, %2;" : "=r"(w_hi) : "f"(e1), "f"(e0));
    float h0 = __uint_as_float(w_hi << 16);
    float h1 = __uint_as_float(w_hi & 0xFFFF0000u);
    float r0 = e0 - h0, r1 = e1 - h1;
    asm("cvt.rn.bf16x2.f32 %0, %1, %2;" : "=r"(w_lo) : "f"(r1), "f"(r0));
}
__device__ __forceinline__ void mma16816(float* c, const uint32_t* a, const uint32_t* b) {
    asm volatile("mma.sync.aligned.m16n8k16.row.col.f32.bf16.bf16.f32 "
        "{%0,%1,%2,%3}, {%4,%5,%6,%7}, {%8,%9}, {%0,%1,%2,%3};"
        : "+f"(c[0]), "+f"(c[1]), "+f"(c[2]), "+f"(c[3])
        : "r"(a[0]), "r"(a[1]), "r"(a[2]), "r"(a[3]), "r"(b[0]), "r"(b[1]));
}
__device__ __forceinline__ void ldsm4(uint32_t* r, uint32_t addr) {
    asm volatile("ldmatrix.sync.aligned.m8n8.x4.shared.b16 {%0,%1,%2,%3}, [%4];"
        : "=r"(r[0]), "=r"(r[1]), "=r"(r[2]), "=r"(r[3]) : "r"(addr));
}

// SMEM row stride 144B (72 bf16): conflict-free for LDSM 8-row x 16B phases.
#define RS 144

// ---------------- prep: split weights into [outer][k] bf16 hi/lo ------------
__global__ void prep_w1_kernel(const float* __restrict__ W1) {
    const int m2 = blockIdx.x, n = threadIdx.x;
    const float* Wm = W1 + (size_t)m2 * 16384;
    #pragma unroll
    for (int j = 0; j < 8; j++) {
        uint32_t h[4], l[4];
        #pragma unroll
        for (int q = 0; q < 4; q++)
            fsplit2(Wm[(8 * j + 2 * q) * 256 + n], Wm[(8 * j + 2 * q + 1) * 256 + n], h[q], l[q]);
        const int idx = (m2 * 256 + n) * 8 + j;
        g_w1hi[idx] = make_uint4(h[0], h[1], h[2], h[3]);
        g_w1lo[idx] = make_uint4(l[0], l[1], l[2], l[3]);
    }
}
__global__ void prep_w2_kernel(const float* __restrict__ W2) {
    const int n1 = blockIdx.x, tid = threadIdx.x;
    const int n2 = tid & 63, kq = tid >> 6;
    const float* Wn = W2 + (size_t)n1 * 16384;
    #pragma unroll
    for (int j = 0; j < 8; j++) {
        const int k0 = kq * 64 + j * 8;
        uint32_t h[4], l[4];
        #pragma unroll
        for (int q = 0; q < 4; q++)
            fsplit2(Wn[(k0 + 2 * q) * 64 + n2], Wn[(k0 + 2 * q + 1) * 64 + n2], h[q], l[q]);
        const int idx = (n1 * 64 + n2) * 32 + kq * 8 + j;
        g_w2hi[idx] = make_uint4(h[0], h[1], h[2], h[3]);
        g_w2lo[idx] = make_uint4(l[0], l[1], l[2], l[3]);
    }
}

// ---------------- stage 1: tile 128(b) x 128(n), K=64 -----------------------
// 8 warps = 8 row-bands of 16; NT=16 (two groups of 8). x read ONCE per CTA.
#define S1_BHI 0
#define S1_BLO 18432
#define S1_SMEM 36864

__global__ void __launch_bounds__(256, 2)
stage1_kernel(const float* __restrict__ x, int bslab) {
    extern __shared__ char smem[];
    const uint32_t sb = (uint32_t)__cvta_generic_to_shared(smem);
    const int tid = threadIdx.x, wid = tid >> 5, lane = tid & 31;
    const int m2 = blockIdx.x, b0 = bslab + blockIdx.y * 128, nbase = blockIdx.z * 128;

    {   // B fill: pre-split images (L2-resident)
        const uint4* bh = g_w1hi + (m2 * 256 + nbase) * 8;
        const uint4* bl = g_w1lo + (m2 * 256 + nbase) * 8;
        #pragma unroll
        for (int i = 0; i < 4; i++) {
            const int idx = tid + 256 * i;
            const int row = idx >> 3, q = idx & 7;
            *(uint4*)(smem + S1_BHI + row * RS + q * 16) = bh[idx];
            *(uint4*)(smem + S1_BLO + row * RS + q * 16) = bl[idx];
        }
    }
    __syncthreads();   // the only barrier

    const int qr = lane >> 2, qc = lane & 3;
    const uint32_t laneB = (uint32_t)(((lane & 7) + ((lane & 16) ? 8 : 0)) * RS +
                                      ((lane & 8) ? 16 : 0));
    const int row0 = b0 + wid * 16 + qr;
    const float* xr0 = x + (size_t)row0 * 4096 + m2 * 64;
    const float* xr1 = xr0 + (size_t)8 * 4096;

    float acc[16][4];
    #pragma unroll
    for (int nt = 0; nt < 16; nt++)
        #pragma unroll
        for (int r = 0; r < 4; r++) acc[nt][r] = 0.f;

    // prime ks=0 x loads
    float2 f[4];
    f[0] = *(const float2*)(xr0 + 2 * qc);
    f[1] = *(const float2*)(xr1 + 2 * qc);
    f[2] = *(const float2*)(xr0 + 2 * qc + 8);
    f[3] = *(const float2*)(xr1 + 2 * qc + 8);

    #pragma unroll
    for (int ks = 0; ks < 4; ks++) {
        float2 nf[4];
        if (ks < 3) {
            const int k0 = (ks + 1) * 16 + 2 * qc;
            nf[0] = *(const float2*)(xr0 + k0);
            nf[1] = *(const float2*)(xr1 + k0);
            nf[2] = *(const float2*)(xr0 + k0 + 8);
            nf[3] = *(const float2*)(xr1 + k0 + 8);
        }
        uint32_t ah[4], al[4];
        fsplit2(f[0].x, f[0].y, ah[0], al[0]);
        fsplit2(f[1].x, f[1].y, ah[1], al[1]);
        fsplit2(f[2].x, f[2].y, ah[2], al[2]);
        fsplit2(f[3].x, f[3].y, ah[3], al[3]);

        #pragma unroll
        for (int h = 0; h < 2; h++) {   // Bh: Ah·Bh + Al·Bh
            uint32_t b[8][2];
            #pragma unroll
            for (int p = 0; p < 4; p++) {
                uint32_t r[4];
                ldsm4(r, sb + S1_BHI + laneB + (h * 4 + p) * 16 * RS + ks * 32);
                b[2 * p][0] = r[0]; b[2 * p][1] = r[1];
                b[2 * p + 1][0] = r[2]; b[2 * p + 1][1] = r[3];
            }
            #pragma unroll
            for (int nt = 0; nt < 8; nt++) {
                mma16816(acc[h * 8 + nt], ah, b[nt]);
                mma16816(acc[h * 8 + nt], al, b[nt]);
            }
        }
        #pragma unroll
        for (int h = 0; h < 2; h++) {   // Bl: Ah·Bl
            uint32_t b[8][2];
            #pragma unroll
            for (int p = 0; p < 4; p++) {
                uint32_t r[4];
                ldsm4(r, sb + S1_BLO + laneB + (h * 4 + p) * 16 * RS + ks * 32);
                b[2 * p][0] = r[0]; b[2 * p][1] = r[1];
                b[2 * p + 1][0] = r[2]; b[2 * p + 1][1] = r[3];
            }
            #pragma unroll
            for (int nt = 0; nt < 8; nt++)
                mma16816(acc[h * 8 + nt], ah, b[nt]);
        }
        if (ks < 3) { f[0] = nf[0]; f[1] = nf[1]; f[2] = nf[2]; f[3] = nf[3]; }
    }

    // epilogue -> g_t fragment-ready words
    uint32_t* gt = (uint32_t*)g_t;
    #pragma unroll
    for (int nt = 0; nt < 16; nt++) {
        const int cg = nbase + nt * 8 + qc * 2;             // n = n1*4 + r
        const size_t base = (((size_t)(cg >> 2) * 64 + m2) * 4096) * 4 + (cg & 3);
        uint32_t whi, wlo;
        fsplit2(acc[nt][0], acc[nt][1], whi, wlo);
        *(uint2*)(gt + base + (size_t)row0 * 4) = make_uint2(whi, wlo);
        fsplit2(acc[nt][2], acc[nt][3], whi, wlo);
        *(uint2*)(gt + base + (size_t)(row0 + 8) * 4) = make_uint2(whi, wlo);
    }
}

// ---------------- stage 2: tile 128(b) x 64(n2), K=256 ----------------------
// 8 warps = 8 row-bands of 16; NT=8. A fragments load-ready from g_t, prefetch g+1.
#define S2_BHI 0                    // [chunk][64][RS] per half (9216 B/chunk)
#define S2_BLO 36864
#define S2_SMEM 73728

__global__ void __launch_bounds__(256, 2)
stage2_kernel(float* __restrict__ y, int bslab) {
    extern __shared__ char smem[];
    const uint32_t sb = (uint32_t)__cvta_generic_to_shared(smem);
    const int tid = threadIdx.x, wid = tid >> 5, lane = tid & 31;
    const int n1 = blockIdx.x, b0 = bslab + blockIdx.y * 128;

    {   // B fill (once): chunked [chunk][n2][RS]
        const uint4* bh = g_w2hi + n1 * 2048;
        const uint4* bl = g_w2lo + n1 * 2048;
        #pragma unroll
        for (int i = 0; i < 8; i++) {
            const int idx = tid + 256 * i;
            const int n2 = idx >> 5, w = idx & 31;
            const int chunk = w >> 3, q = w & 7;
            const int dst = chunk * 9216 + n2 * RS + q * 16;
            *(uint4*)(smem + S2_BHI + dst) = bh[idx];
            *(uint4*)(smem + S2_BLO + dst) = bl[idx];
        }
    }
    __syncthreads();   // the only barrier

    const int qr = lane >> 2, qc = lane & 3;
    const uint32_t laneB = (uint32_t)(((lane & 7) + ((lane & 16) ? 8 : 0)) * RS +
                                      ((lane & 8) ? 16 : 0));
    const int qch = qc >> 1, rr = (qc & 1) * 2;   // m2 parity, r-pair slot
    const int row0 = b0 + wid * 16 + qr;

    float acc[8][4];
    #pragma unroll
    for (int nt = 0; nt < 8; nt++)
        #pragma unroll
        for (int r = 0; r < 4; r++) acc[nt][r] = 0.f;

    const uint32_t* tb = (const uint32_t*)g_t + (size_t)n1 * 64 * 16384;

    // prime: g=0 raw A (4 x uint2 = (ah, al) pairs, fragment-ready)
    uint2 cur[4];
    {
        const uint32_t* pA = tb + (size_t)qch * 16384;
        const uint32_t* pB = pA + 2 * 16384;
        cur[0] = *(const uint2*)(pA + (size_t)row0 * 4 + rr);
        cur[1] = *(const uint2*)(pA + (size_t)(row0 + 8) * 4 + rr);
        cur[2] = *(const uint2*)(pB + (size_t)row0 * 4 + rr);
        cur[3] = *(const uint2*)(pB + (size_t)(row0 + 8) * 4 + rr);
    }

    #pragma unroll
    for (int g = 0; g < 16; g++) {                  // g = global k16 index
        uint2 nxt[4];
        if (g < 15) {
            const uint32_t* pA = tb + (size_t)(4 * (g + 1) + qch) * 16384;
            const uint32_t* pB = pA + 2 * 16384;
            nxt[0] = *(const uint2*)(pA + (size_t)row0 * 4 + rr);
            nxt[1] = *(const uint2*)(pA + (size_t)(row0 + 8) * 4 + rr);
            nxt[2] = *(const uint2*)(pB + (size_t)row0 * 4 + rr);
            nxt[3] = *(const uint2*)(pB + (size_t)(row0 + 8) * 4 + rr);
        }
        uint32_t ah[4] = {cur[0].x, cur[1].x, cur[2].x, cur[3].x};
        uint32_t al[4] = {cur[0].y, cur[1].y, cur[2].y, cur[3].y};

        const int ch = g >> 2, ksl = g & 3;
        uint32_t b[8][2];
        {   // Bh plane: Ah·Bh + Al·Bh
            #pragma unroll
            for (int p = 0; p < 4; p++) {
                uint32_t r[4];
                ldsm4(r, sb + S2_BHI + ch * 9216 + laneB + p * 16 * RS + ksl * 32);
                b[2 * p][0] = r[0]; b[2 * p][1] = r[1];
                b[2 * p + 1][0] = r[2]; b[2 * p + 1][1] = r[3];
            }
            #pragma unroll
            for (int nt = 0; nt < 8; nt++) {
                mma16816(acc[nt], ah, b[nt]);
                mma16816(acc[nt], al, b[nt]);
            }
        }
        {   // Bl plane: Ah·Bl (reuse b regs)
            #pragma unroll
            for (int p = 0; p < 4; p++) {
                uint32_t r[4];
                ldsm4(r, sb + S2_BLO + ch * 9216 + laneB + p * 16 * RS + ksl * 32);
                b[2 * p][0] = r[0]; b[2 * p][1] = r[1];
                b[2 * p + 1][0] = r[2]; b[2 * p + 1][1] = r[3];
            }
            #pragma unroll
            for (int nt = 0; nt < 8; nt++)
                mma16816(acc[nt], ah, b[nt]);
        }
        if (g < 15) { cur[0] = nxt[0]; cur[1] = nxt[1]; cur[2] = nxt[2]; cur[3] = nxt[3]; }
    }

    // epilogue: y[b][n1*64 + n2]
    #pragma unroll
    for (int nt = 0; nt < 8; nt++) {
        const int col = n1 * 64 + nt * 8 + qc * 2;
        *(float2*)(y + (size_t)row0 * 4096 + col) = make_float2(acc[nt][0], acc[nt][1]);
        *(float2*)(y + (size_t)(row0 + 8) * 4096 + col) = make_float2(acc[nt][2], acc[nt][3]);
    }
}

// ---------------------------------------------------------------------------
extern "C" void kernel_launch(void* const* d_in, const int* in_sizes, int n_in,
                              void* d_out, int out_size) {
    const float* x  = (const float*)d_in[0];
    const float* W1 = (const float*)d_in[1];
    const float* W2 = (const float*)d_in[2];
    float* y = (float*)d_out;

    cudaFuncSetAttribute(stage1_kernel, cudaFuncAttributeMaxDynamicSharedMemorySize, S1_SMEM);
    cudaFuncSetAttribute(stage2_kernel, cudaFuncAttributeMaxDynamicSharedMemorySize, S2_SMEM);

    prep_w1_kernel<<<64, 256>>>(W1);
    prep_w2_kernel<<<64, 256>>>(W2);
    // Interleave slabs so each slab's t (64MB) is consumed while L2-resident.
    for (int s = 0; s < 4; s++) {
        stage1_kernel<<<dim3(64, SLAB / 128, 2), 256, S1_SMEM>>>(x, s * SLAB);
        stage2_kernel<<<dim3(64, SLAB / 128), 256, S2_SMEM>>>(y, s * SLAB);
    }
}